// round 17
// baseline (speedup 1.0000x reference)
#include <cuda_runtime.h>
#include <math.h>

#define NBATCH 16
#define IH 512
#define IW 512
#define CH2 256
#define CW2 256
#define PLANE_Y (NBATCH * IH * IW)
#define PLANE_C (NBATCH * CH2 * CW2)

#define NT_Y (NBATCH * 64 * 64)   // 65536 luma tiles
#define NT_C (NBATCH * 32 * 32)   // 16384 chroma tiles per plane
#define NT_ALL (NT_Y + 2 * NT_C)  // 98304

// ---- scratch planes (static device globals; no runtime allocation) ----
__device__ float g_Y[PLANE_Y];
__device__ float g_U[PLANE_C];
__device__ float g_V[PLANE_C];
__device__ float g_rY[PLANE_Y];
__device__ float g_rU[PLANE_C];
__device__ float g_rV[PLANE_C];

// ---- compile-time DCT tables, replicating numpy fp64->fp32 exactly ----
__host__ __device__ constexpr double kCosV(int k) {
    return (k == 0) ? 1.0
         : (k == 1) ? 0.98078528040323044913
         : (k == 2) ? 0.92387953251128675613
         : (k == 3) ? 0.83146961230254523708
         : (k == 4) ? 0.70710678118654752440
         : (k == 5) ? 0.55557023301960222474
         : (k == 6) ? 0.38268343236508977173
         : (k == 7) ? 0.19509032201612826785
         : 0.0;
}
__host__ __device__ constexpr double cos16(int k) {
    k &= 31;
    if (k > 16) k = 32 - k;
    return (k <= 8) ? kCosV(k) : -kCosV(16 - k);
}
__host__ __device__ constexpr float Dc(int i, int j) {
    return (float)((j == 0) ? 0.35355339059327376220
                            : 0.5 * cos16((2 * i + 1) * j));
}
struct WTab { float w[64][64]; };
__host__ __device__ constexpr WTab makeW() {
    WTab t{};
    for (int p = 0; p < 64; p++)
        for (int f = 0; f < 64; f++)
            t.w[p][f] = Dc(p >> 3, f >> 3) * Dc(p & 7, f & 7);  // fp32 product (jnp.kron)
    return t;
}
__device__ constexpr WTab WT = makeW();

// ---- tile geometry helper (unified Y/U/V tile index) ----
struct TileInfo {
    const float* plane;
    float*       rec;
    float*       qbase;
    int          width;
    int          qsel;
    size_t       po;
    int          tp;
};

__device__ __forceinline__ TileInfo tile_info(int tile, float* qY, float* qU, float* qV)
{
    TileInfo ti;
    int tp, nbx, height;
    if (tile < NT_Y) {
        tp = tile;           ti.plane = g_Y; ti.rec = g_rY; ti.qbase = qY;
        ti.width = IW;  height = IH;  ti.qsel = 0;
    } else if (tile < NT_Y + NT_C) {
        tp = tile - NT_Y;    ti.plane = g_U; ti.rec = g_rU; ti.qbase = qU;
        ti.width = CW2; height = CH2; ti.qsel = 1;
    } else {
        tp = tile - NT_Y - NT_C; ti.plane = g_V; ti.rec = g_rV; ti.qbase = qV;
        ti.width = CW2; height = CH2; ti.qsel = 1;
    }
    nbx = ti.width >> 3;
    int nbpi = (height >> 3) * nbx;
    int b  = tp / nbpi, r = tp - b * nbpi;
    int by = r / nbx,  bx = r - by * nbx;
    ti.po = ((size_t)b * height + by * 8) * ti.width + bx * 8;
    ti.tp = tp;
    return ti;
}

// ---- RGB -> YUV (+128 chroma) + 2x2 pairwise mean: 2 chroma sites/thread ----
// Per-pixel arithmetic and mean order identical to validated version.
__global__ void k_csc(const float* __restrict__ img)
{
    int t = blockIdx.x * blockDim.x + threadIdx.x;
    if (t >= PLANE_C / 2) return;
    int cx2 = t & 127;          // pair of chroma sites
    int cy  = (t >> 7) & 255;
    int b   = t >> 15;
    int cx0 = cx2 * 2;

    const float* Rp = img + (size_t)b * 3 * IH * IW;
    const float* Gp = Rp + IH * IW;
    const float* Bp = Rp + 2 * IH * IW;
    int o0 = (cy * 2) * IW + cx0 * 2;
    int o1 = o0 + IW;
    float4 r0 = *(const float4*)(Rp + o0), r1 = *(const float4*)(Rp + o1);
    float4 g0 = *(const float4*)(Gp + o0), g1 = *(const float4*)(Gp + o1);
    float4 b0 = *(const float4*)(Bp + o0), b1 = *(const float4*)(Bp + o1);

    float rr[8] = {r0.x, r0.y, r0.z, r0.w, r1.x, r1.y, r1.z, r1.w};
    float gg[8] = {g0.x, g0.y, g0.z, g0.w, g1.x, g1.y, g1.z, g1.w};
    float bb[8] = {b0.x, b0.y, b0.z, b0.w, b1.x, b1.y, b1.z, b1.w};
    float y[8], u[8], v[8];
#pragma unroll
    for (int i = 0; i < 8; i++) {
        float r  = __fmul_rn(rr[i], 255.0f);
        float g  = __fmul_rn(gg[i], 255.0f);
        float bl = __fmul_rn(bb[i], 255.0f);
        y[i] = __fadd_rn(__fadd_rn(__fmul_rn(r, 0.299f),
                                   __fmul_rn(g, 0.587f)),
                         __fmul_rn(bl, 0.114f));
        u[i] = __fadd_rn(__fadd_rn(__fadd_rn(__fmul_rn(r, -0.168736f),
                                             __fmul_rn(g, -0.331264f)),
                                   __fmul_rn(bl, 0.5f)), 128.0f);
        v[i] = __fadd_rn(__fadd_rn(__fadd_rn(__fmul_rn(r, 0.5f),
                                             __fmul_rn(g, -0.418688f)),
                                   __fmul_rn(bl, -0.081312f)), 128.0f);
    }
    float* yb = g_Y + (size_t)b * IH * IW;
    *(float4*)(yb + o0) = make_float4(y[0], y[1], y[2], y[3]);
    *(float4*)(yb + o1) = make_float4(y[4], y[5], y[6], y[7]);
    // site 0 uses cols {0,1}, site 1 uses cols {2,3}; pairwise order:
    // (top-left + top-right) + (bot-left + bot-right), then *0.25
    float u0 = __fmul_rn(__fadd_rn(__fadd_rn(u[0], u[1]), __fadd_rn(u[4], u[5])), 0.25f);
    float u1 = __fmul_rn(__fadd_rn(__fadd_rn(u[2], u[3]), __fadd_rn(u[6], u[7])), 0.25f);
    float v0 = __fmul_rn(__fadd_rn(__fadd_rn(v[0], v[1]), __fadd_rn(v[4], v[5])), 0.25f);
    float v1 = __fmul_rn(__fadd_rn(__fadd_rn(v[2], v[3]), __fadd_rn(v[6], v[7])), 0.25f);
    int co = ((b << 8) + cy) * CW2 + cx0;
    *(float2*)(g_U + co) = make_float2(u0, u1);
    *(float2*)(g_V + co) = make_float2(v0, v1);
}

// ---- forward accumulation for f-group FG (R9-validated) ----
template<int FG>
__device__ __forceinline__ void fwd_accum(const float* __restrict__ xs, float a[8])
{
#pragma unroll
    for (int pp = 0; pp < 64; pp++) {
        float xv = xs[pp];
#pragma unroll
        for (int u = 0; u < 8; u++)
            a[u] = fmaf(xv, WT.w[pp][FG * 8 + u], a[u]);
    }
}

// ---- inverse rows for output row R (immediate D consts; R9-validated) ----
template<int R>
__device__ __forceinline__ void inv_rows(const float* __restrict__ Cs, float o[8])
{
    float T[8];
#pragma unroll
    for (int j2 = 0; j2 < 8; j2++) {
        float s = 0.f;
#pragma unroll
        for (int j1 = 0; j1 < 8; j1++)
            s = fmaf(Dc(R, j1), Cs[j1 * 8 + j2], s);
        T[j2] = s;
    }
#pragma unroll
    for (int c = 0; c < 8; c++) {
        float s = 0.f;
#pragma unroll
        for (int j2 = 0; j2 < 8; j2++)
            s = fmaf(T[j2], Dc(c, j2), s);
        o[c] = s + 128.f;
    }
}

// ---- fused forward DCT + quantize + dequant + inverse DCT (R16, best) ----
__global__ void __launch_bounds__(256) k_fwd_inv(const float* __restrict__ lq,
                                                 const float* __restrict__ cq,
                                                 float* __restrict__ qY,
                                                 float* __restrict__ qU,
                                                 float* __restrict__ qV)
{
    __shared__ float xs[32 * 65];   // x in phase 1, reused as C in phase 3
    __shared__ float Qs[2][64];

    int t = threadIdx.x;
    if (t < 64)              Qs[0][t]      = lq[t];
    else if (t < 128)        Qs[1][t - 64] = cq[t - 64];

    {
        int tileL = t & 31;
        int row   = t >> 5;
        int tile  = blockIdx.x * 32 + tileL;
        TileInfo ti = tile_info(tile, qY, qU, qV);
        const float* p = ti.plane + ti.po + (size_t)row * ti.width;
        float4 v0 = *(const float4*)(p);
        float4 v1 = *(const float4*)(p + 4);
        float* xr = xs + tileL * 65 + row * 8;
        xr[0] = v0.x - 128.f; xr[1] = v0.y - 128.f; xr[2] = v0.z - 128.f; xr[3] = v0.w - 128.f;
        xr[4] = v1.x - 128.f; xr[5] = v1.y - 128.f; xr[6] = v1.z - 128.f; xr[7] = v1.w - 128.f;
    }
    __syncthreads();

    int wid  = t >> 5;
    int lane = t & 31;
    int tile = blockIdx.x * 32 + lane;
    TileInfo ti = tile_info(tile, qY, qU, qV);

    float a[8] = {0.f, 0.f, 0.f, 0.f, 0.f, 0.f, 0.f, 0.f};
    const float* xl = xs + lane * 65;
    switch (wid) {
        case 0: fwd_accum<0>(xl, a); break;
        case 1: fwd_accum<1>(xl, a); break;
        case 2: fwd_accum<2>(xl, a); break;
        case 3: fwd_accum<3>(xl, a); break;
        case 4: fwd_accum<4>(xl, a); break;
        case 5: fwd_accum<5>(xl, a); break;
        case 6: fwd_accum<6>(xl, a); break;
        case 7: fwd_accum<7>(xl, a); break;
    }

    float q[8];
    const float* Qt = Qs[ti.qsel] + wid * 8;
#pragma unroll
    for (int u = 0; u < 8; u++)
        q[u] = rintf(__fdiv_rn(a[u], Qt[u]));

    float* qo = ti.qbase + (size_t)ti.tp * 64 + wid * 8;
    *(float4*)(qo)     = make_float4(q[0], q[1], q[2], q[3]);
    *(float4*)(qo + 4) = make_float4(q[4], q[5], q[6], q[7]);

    // ---- inverse tail ----
    __syncthreads();
    {
        float* cr = xs + lane * 65 + wid * 8;
        cr[0] = __fmul_rn(q[0], Qt[0]); cr[1] = __fmul_rn(q[1], Qt[1]);
        cr[2] = __fmul_rn(q[2], Qt[2]); cr[3] = __fmul_rn(q[3], Qt[3]);
        cr[4] = __fmul_rn(q[4], Qt[4]); cr[5] = __fmul_rn(q[5], Qt[5]);
        cr[6] = __fmul_rn(q[6], Qt[6]); cr[7] = __fmul_rn(q[7], Qt[7]);
    }
    __syncthreads();

    float o[8];
    const float* cl = xs + lane * 65;
    switch (wid) {
        case 0: inv_rows<0>(cl, o); break;
        case 1: inv_rows<1>(cl, o); break;
        case 2: inv_rows<2>(cl, o); break;
        case 3: inv_rows<3>(cl, o); break;
        case 4: inv_rows<4>(cl, o); break;
        case 5: inv_rows<5>(cl, o); break;
        case 6: inv_rows<6>(cl, o); break;
        case 7: inv_rows<7>(cl, o); break;
    }

    float* rp = ti.rec + ti.po + (size_t)wid * ti.width;
    *(float4*)(rp)     = make_float4(o[0], o[1], o[2], o[3]);
    *(float4*)(rp + 4) = make_float4(o[4], o[5], o[6], o[7]);
}

// ---- quad recon with warp-shared vertical lerps ----
// Lane loads ONLY its own chroma column (3 U + 3 V), computes its vertical
// lerps; neighbor columns' lerps come from shuffles (identical formula +
// identical inputs -> bit-identical to R9 quad recon). Edge lanes compute
// the out-of-warp neighbor column locally.
__global__ void __launch_bounds__(256) k_recon(float* __restrict__ out)
{
    int t = blockIdx.x * blockDim.x + threadIdx.x;
    if (t >= PLANE_C) return;
    int cx = t & 255;
    int cy = (t >> 8) & 255;
    int b  = t >> 16;
    int lane = threadIdx.x & 31;

    size_t cb = (size_t)b * CH2 * CW2;
    const float* Up = g_rU + cb;
    const float* Vp = g_rV + cb;

    int cym = max(cy - 1, 0), cyp = min(cy + 1, 255);
    bool y_top = (cy == 0), y_bot = (cy == 255);
    bool x_lft = (cx == 0), x_rgt = (cx == 255);

    // own column vertical lerps
    float ua = Up[cym * CW2 + cx], um = Up[cy * CW2 + cx], up = Up[cyp * CW2 + cx];
    float va = Vp[cym * CW2 + cx], vm = Vp[cy * CW2 + cx], vp = Vp[cyp * CW2 + cx];
    float ue = y_top ? um : __fadd_rn(__fmul_rn(ua, 0.25f), __fmul_rn(um, 0.75f));
    float uo = y_bot ? um : __fadd_rn(__fmul_rn(um, 0.75f), __fmul_rn(up, 0.25f));
    float ve = y_top ? vm : __fadd_rn(__fmul_rn(va, 0.25f), __fmul_rn(vm, 0.75f));
    float vo = y_bot ? vm : __fadd_rn(__fmul_rn(vm, 0.75f), __fmul_rn(vp, 0.25f));

    // neighbor columns via shuffle
    float ueL = __shfl_up_sync(0xffffffffu, ue, 1);
    float uoL = __shfl_up_sync(0xffffffffu, uo, 1);
    float veL = __shfl_up_sync(0xffffffffu, ve, 1);
    float voL = __shfl_up_sync(0xffffffffu, vo, 1);
    float ueR = __shfl_down_sync(0xffffffffu, ue, 1);
    float uoR = __shfl_down_sync(0xffffffffu, uo, 1);
    float veR = __shfl_down_sync(0xffffffffu, ve, 1);
    float voR = __shfl_down_sync(0xffffffffu, vo, 1);

    if (lane == 0 && !x_lft) {
        int c = cx - 1;
        float a2 = Up[cym * CW2 + c], m2 = Up[cy * CW2 + c], p2 = Up[cyp * CW2 + c];
        float a3 = Vp[cym * CW2 + c], m3 = Vp[cy * CW2 + c], p3 = Vp[cyp * CW2 + c];
        ueL = y_top ? m2 : __fadd_rn(__fmul_rn(a2, 0.25f), __fmul_rn(m2, 0.75f));
        uoL = y_bot ? m2 : __fadd_rn(__fmul_rn(m2, 0.75f), __fmul_rn(p2, 0.25f));
        veL = y_top ? m3 : __fadd_rn(__fmul_rn(a3, 0.25f), __fmul_rn(m3, 0.75f));
        voL = y_bot ? m3 : __fadd_rn(__fmul_rn(m3, 0.75f), __fmul_rn(p3, 0.25f));
    }
    if (lane == 31 && !x_rgt) {
        int c = cx + 1;
        float a2 = Up[cym * CW2 + c], m2 = Up[cy * CW2 + c], p2 = Up[cyp * CW2 + c];
        float a3 = Vp[cym * CW2 + c], m3 = Vp[cy * CW2 + c], p3 = Vp[cyp * CW2 + c];
        ueR = y_top ? m2 : __fadd_rn(__fmul_rn(a2, 0.25f), __fmul_rn(m2, 0.75f));
        uoR = y_bot ? m2 : __fadd_rn(__fmul_rn(m2, 0.75f), __fmul_rn(p2, 0.25f));
        veR = y_top ? m3 : __fadd_rn(__fmul_rn(a3, 0.25f), __fmul_rn(m3, 0.75f));
        voR = y_bot ? m3 : __fadd_rn(__fmul_rn(m3, 0.75f), __fmul_rn(p3, 0.25f));
    }

    // horizontal lerps (same expressions/edge selections as validated quad)
    float u00 = x_lft ? ue : __fadd_rn(__fmul_rn(ueL, 0.25f), __fmul_rn(ue, 0.75f));
    float u01 = x_rgt ? ue : __fadd_rn(__fmul_rn(ue, 0.75f), __fmul_rn(ueR, 0.25f));
    float u10 = x_lft ? uo : __fadd_rn(__fmul_rn(uoL, 0.25f), __fmul_rn(uo, 0.75f));
    float u11 = x_rgt ? uo : __fadd_rn(__fmul_rn(uo, 0.75f), __fmul_rn(uoR, 0.25f));
    float v00 = x_lft ? ve : __fadd_rn(__fmul_rn(veL, 0.25f), __fmul_rn(ve, 0.75f));
    float v01 = x_rgt ? ve : __fadd_rn(__fmul_rn(ve, 0.75f), __fmul_rn(veR, 0.25f));
    float v10 = x_lft ? vo : __fadd_rn(__fmul_rn(voL, 0.25f), __fmul_rn(vo, 0.75f));
    float v11 = x_rgt ? vo : __fadd_rn(__fmul_rn(vo, 0.75f), __fmul_rn(voR, 0.25f));

    size_t yo0 = ((size_t)b * IH + cy * 2) * IW + cx * 2;
    size_t yo1 = yo0 + IW;
    float2 yr0 = *(const float2*)(g_rY + yo0);
    float2 yr1 = *(const float2*)(g_rY + yo1);

    float yq[4] = {yr0.x, yr0.y, yr1.x, yr1.y};
    float uq[4] = {u00, u01, u10, u11};
    float vq[4] = {v00, v01, v10, v11};
    float R[4], G[4], B[4];
#pragma unroll
    for (int i = 0; i < 4; i++) {
        float uu = __fadd_rn(uq[i], -128.0f);
        float vv = __fadd_rn(vq[i], -128.0f);
        float yv = yq[i];
        float r  = __fadd_rn(yv, __fmul_rn(vv, 1.402f));
        float g  = __fadd_rn(__fadd_rn(yv, __fmul_rn(uu, -0.344136f)), __fmul_rn(vv, -0.714136f));
        float bl = __fadd_rn(yv, __fmul_rn(uu, 1.772f));
        R[i] = __fdiv_rn(fminf(fmaxf(r,  0.f), 255.f), 255.0f);
        G[i] = __fdiv_rn(fminf(fmaxf(g,  0.f), 255.f), 255.0f);
        B[i] = __fdiv_rn(fminf(fmaxf(bl, 0.f), 255.f), 255.0f);
    }

    size_t ob0 = (size_t)b * 3 * IH * IW + ((size_t)cy * 2) * IW + cx * 2;
    size_t ob1 = ob0 + IW;
    *(float2*)(out + ob0)                 = make_float2(R[0], R[1]);
    *(float2*)(out + ob1)                 = make_float2(R[2], R[3]);
    *(float2*)(out + ob0 + IH * IW)       = make_float2(G[0], G[1]);
    *(float2*)(out + ob1 + IH * IW)       = make_float2(G[2], G[3]);
    *(float2*)(out + ob0 + 2 * IH * IW)   = make_float2(B[0], B[1]);
    *(float2*)(out + ob1 + 2 * IH * IW)   = make_float2(B[2], B[3]);
}

extern "C" void kernel_launch(void* const* d_in, const int* in_sizes, int n_in,
                              void* d_out, int out_size)
{
    const float* img = (const float*)d_in[0];
    const float* lq  = (const float*)d_in[1];
    const float* cq  = (const float*)d_in[2];
    float* out = (float*)d_out;

    // output layout: rgb | qY | qU | qV (reference return order, flattened)
    float* qY = out + 12582912;
    float* qU = out + 16777216;
    float* qV = out + 17825792;

    k_csc<<<(PLANE_C / 2 + 255) / 256, 256>>>(img);
    k_fwd_inv<<<NT_ALL / 32, 256>>>(lq, cq, qY, qU, qV);
    k_recon<<<(PLANE_C + 255) / 256, 256>>>(out);
}